// round 11
// baseline (speedup 1.0000x reference)
#include <cuda_runtime.h>

#define IMG_H 512
#define IMG_W 512
#define NIMG  16
#define TW    32
#define TH    32
#define RH    42            // TH + 10 halo rows of hblur
#define HSTR2 33            // hblur stride in ulonglong2 (16B) units
#define NPIX  (NIMG * IMG_H * IMG_W)
#define NBLK  (NIMG * (IMG_H / TH) * (IMG_W / TW))   // 4096

typedef unsigned long long u64;

__device__ float        g_part[NBLK];
__device__ unsigned int g_count;     // zero-init at load; reset by last block

// ---- packed f32x2 helpers (sm_100+; ptxas never emits these from C++) ----
__device__ __forceinline__ u64 pk(float lo, float hi) {
    u64 r; asm("mov.b64 %0, {%1, %2};" : "=l"(r) : "f"(lo), "f"(hi)); return r;
}
__device__ __forceinline__ void upk(float& lo, float& hi, u64 v) {
    asm("mov.b64 {%0, %1}, %2;" : "=f"(lo), "=f"(hi) : "l"(v));
}
__device__ __forceinline__ u64 fma2(u64 a, u64 b, u64 c) {
    u64 d; asm("fma.rn.f32x2 %0, %1, %2, %3;" : "=l"(d) : "l"(a), "l"(b), "l"(c)); return d;
}
__device__ __forceinline__ u64 mul2(u64 a, u64 b) {
    u64 d; asm("mul.rn.f32x2 %0, %1, %2;" : "=l"(d) : "l"(a), "l"(b)); return d;
}

__global__ void __launch_bounds__(256, 4) ssim_kernel(
    const float* __restrict__ fused,
    const float* __restrict__ imga,
    const float* __restrict__ imgb,
    float* __restrict__ out)
{
    // Channel-interleaved hblur: hbA[y][x] = (acc0, acc1) = ((muF,muA),(muB,eF2))
    //                            hbB[y][x] = (acc2, acc3) = ((eA2,eB2),(eFA,eFB))
    extern __shared__ ulonglong2 smem2[];
    ulonglong2* hbA = smem2;                   // [RH][HSTR2]
    ulonglong2* hbB = hbA + RH * HSTR2;        // [RH][HSTR2]

    constexpr float GW[11] = {
        0.00102838f, 0.00759876f, 0.03600077f, 0.10936069f, 0.21300553f,
        0.26601172f,
        0.21300553f, 0.10936069f, 0.03600077f, 0.00759876f, 0.00102838f};
    const float c1 = 0.0001f;
    const float c2 = 0.0009f;

    const int tid = threadIdx.x;
    const int bx  = blockIdx.x;
    const int gy0 = blockIdx.y * TH - 5;
    const size_t base = (size_t)blockIdx.z * (IMG_H * IMG_W);
    const float* fP = fused + base;
    const float* aP = imga + base;
    const float* bP = imgb + base;
    const bool edge_x = (bx == 0) | (bx == (IMG_W / TW) - 1);

    // ---- Stage 1: horizontal blur straight from gmem, 4 outputs/task ----
    // Packed-channel accumulators; products formed in registers.
    for (int t = tid; t < RH * 8; t += 256) {
        const int y  = t >> 3;
        const int x0 = (t & 7) * 4;
        const int gy = gy0 + y;

        u64 acc[4][4];
#pragma unroll
        for (int j = 0; j < 4; j++)
#pragma unroll
            for (int c = 0; c < 4; c++) acc[j][c] = 0ull;

        if (gy >= 0 && gy < IMG_H) {
            if (!edge_x) {
                const int gxa = bx * TW + x0 - 8;       // multiple of 4, >=24
                const float4* f4 = (const float4*)(fP + gy * IMG_W + gxa);
                const float4* a4 = (const float4*)(aP + gy * IMG_W + gxa);
                const float4* b4 = (const float4*)(bP + gy * IMG_W + gxa);
#pragma unroll
                for (int q = 0; q < 5; q++) {
                    float4 fv = f4[q], av = a4[q], bv = b4[q];
                    float fs[4] = {fv.x, fv.y, fv.z, fv.w};
                    float as[4] = {av.x, av.y, av.z, av.w};
                    float bs[4] = {bv.x, bv.y, bv.z, bv.w};
#pragma unroll
                    for (int m = 0; m < 4; m++) {
                        int k = q * 4 + m - 3;          // window px 0..13
                        if (k < 0 || k >= 14) continue;
                        float f = fmaf(fs[m], 0.5f, 0.5f);
                        float a = fmaf(as[m], 0.5f, 0.5f);
                        float b = fmaf(bs[m], 0.5f, 0.5f);
                        u64 ab = pk(a, b);
                        u64 P0 = pk(f, a);              // (f , a )
                        u64 P1 = pk(b, f * f);          // (b , f2)
                        u64 P2 = mul2(ab, ab);          // (a2, b2)
                        u64 P3 = mul2(pk(f, f), ab);    // (fa, fb)
#pragma unroll
                        for (int j = 0; j < 4; j++) {
                            int tt = k - j;             // compile-time
                            if (tt >= 0 && tt < 11) {
                                u64 w = pk(GW[tt], GW[tt]);
                                acc[j][0] = fma2(P0, w, acc[j][0]);
                                acc[j][1] = fma2(P1, w, acc[j][1]);
                                acc[j][2] = fma2(P2, w, acc[j][2]);
                                acc[j][3] = fma2(P3, w, acc[j][3]);
                            }
                        }
                    }
                }
            } else {
                const int gxw = bx * TW + x0 - 5;
                const float* frow = fP + gy * IMG_W;
                const float* arow = aP + gy * IMG_W;
                const float* brow = bP + gy * IMG_W;
#pragma unroll
                for (int k = 0; k < 14; k++) {
                    int gx = gxw + k;
                    float f = 0.5f, a = 0.5f, b = 0.5f;
                    if (gx >= 0 && gx < IMG_W) {
                        f = fmaf(frow[gx], 0.5f, 0.5f);
                        a = fmaf(arow[gx], 0.5f, 0.5f);
                        b = fmaf(brow[gx], 0.5f, 0.5f);
                    } else { f = 0.f; a = 0.f; b = 0.f; }
                    u64 ab = pk(a, b);
                    u64 P0 = pk(f, a);
                    u64 P1 = pk(b, f * f);
                    u64 P2 = mul2(ab, ab);
                    u64 P3 = mul2(pk(f, f), ab);
#pragma unroll
                    for (int j = 0; j < 4; j++) {
                        int tt = k - j;
                        if (tt >= 0 && tt < 11) {
                            u64 w = pk(GW[tt], GW[tt]);
                            acc[j][0] = fma2(P0, w, acc[j][0]);
                            acc[j][1] = fma2(P1, w, acc[j][1]);
                            acc[j][2] = fma2(P2, w, acc[j][2]);
                            acc[j][3] = fma2(P3, w, acc[j][3]);
                        }
                    }
                }
            }
        }

        ulonglong2* pA = hbA + y * HSTR2 + x0;
        ulonglong2* pB = hbB + y * HSTR2 + x0;
#pragma unroll
        for (int j = 0; j < 4; j++) {
            pA[j] = make_ulonglong2(acc[j][0], acc[j][1]);
            pB[j] = make_ulonglong2(acc[j][2], acc[j][3]);
        }
    }
    __syncthreads();

    // ---- Stage 2: vertical blur (4 outputs/thread) + SSIM ----
    float lsum = 0.f;
    {
        const int x  = tid & 31;
        const int yb = (tid >> 5) * 4;

        u64 acc[4][4];
#pragma unroll
        for (int j = 0; j < 4; j++)
#pragma unroll
            for (int c = 0; c < 4; c++) acc[j][c] = 0ull;

#pragma unroll
        for (int r = 0; r < 14; r++) {
            ulonglong2 qA = hbA[(yb + r) * HSTR2 + x];
            ulonglong2 qB = hbB[(yb + r) * HSTR2 + x];
#pragma unroll
            for (int j = 0; j < 4; j++) {
                int tt = r - j;
                if (tt >= 0 && tt < 11) {
                    u64 w = pk(GW[tt], GW[tt]);
                    acc[j][0] = fma2(qA.x, w, acc[j][0]);
                    acc[j][1] = fma2(qA.y, w, acc[j][1]);
                    acc[j][2] = fma2(qB.x, w, acc[j][2]);
                    acc[j][3] = fma2(qB.y, w, acc[j][3]);
                }
            }
        }

#pragma unroll
        for (int j = 0; j < 4; j++) {
            float muF, muA, muB, eF2, eA2, eB2, eFA, eFB;
            upk(muF, muA, acc[j][0]);
            upk(muB, eF2, acc[j][1]);
            upk(eA2, eB2, acc[j][2]);
            upk(eFA, eFB, acc[j][3]);
            float muF2 = muF * muF;
            float sF2  = eF2 - muF2;
            float muA2 = muA * muA;
            float m12a = muF * muA;
            float sA2  = eA2 - muA2;
            float s12a = eFA - m12a;
            float na   = (2.f * m12a + c1) * (2.f * s12a + c2);
            float da   = (muF2 + muA2 + c1) * (sF2 + sA2 + c2);
            float muB2 = muB * muB;
            float m12b = muF * muB;
            float sB2  = eB2 - muB2;
            float s12b = eFB - m12b;
            float nb   = (2.f * m12b + c1) * (2.f * s12b + c2);
            float db   = (muF2 + muB2 + c1) * (sF2 + sB2 + c2);
            float num = fmaf(na, db, nb * da);
            lsum += __fdividef(num, da * db);
        }
    }

    // ---- Block reduction -> deterministic per-block partial ----
#pragma unroll
    for (int o = 16; o > 0; o >>= 1)
        lsum += __shfl_down_sync(0xffffffffu, lsum, o);

    __shared__ float wsum[8];
    __shared__ bool  is_last;
    if ((tid & 31) == 0) wsum[tid >> 5] = lsum;
    __syncthreads();
    if (tid == 0) {
        float v = 0.f;
#pragma unroll
        for (int w = 0; w < 8; w++) v += wsum[w];
        int bi = ((int)blockIdx.z * gridDim.y + blockIdx.y) * gridDim.x
                 + blockIdx.x;
        g_part[bi] = v;
        __threadfence();
        unsigned prev = atomicAdd(&g_count, 1u);
        is_last = (prev == NBLK - 1);
    }
    __syncthreads();

    if (is_last) {
        double s = 0.0;
        for (int i = tid; i < NBLK; i += 256) s += (double)g_part[i];
#pragma unroll
        for (int o = 16; o > 0; o >>= 1)
            s += __shfl_down_sync(0xffffffffu, s, o);
        __shared__ double dsum[8];
        if ((tid & 31) == 0) dsum[tid >> 5] = s;
        __syncthreads();
        if (tid == 0) {
            double tot = 0.0;
#pragma unroll
            for (int w = 0; w < 8; w++) tot += dsum[w];
            out[0] = (float)(1.0 - tot / (2.0 * (double)NPIX));
            g_count = 0;      // reset for next graph replay
        }
    }
}

extern "C" void kernel_launch(void* const* d_in, const int* in_sizes, int n_in,
                              void* d_out, int out_size)
{
    (void)in_sizes; (void)n_in; (void)out_size;
    const float* fused = (const float*)d_in[0];
    const float* imga  = (const float*)d_in[1];
    const float* imgb  = (const float*)d_in[2];

    const size_t smem_bytes = (size_t)(2 * RH * HSTR2) * sizeof(ulonglong2); // 44.4 KB
    cudaFuncSetAttribute(ssim_kernel,
                         cudaFuncAttributeMaxDynamicSharedMemorySize,
                         (int)smem_bytes);

    dim3 grid(IMG_W / TW, IMG_H / TH, NIMG);
    ssim_kernel<<<grid, 256, smem_bytes>>>(fused, imga, imgb, (float*)d_out);
}